// round 13
// baseline (speedup 1.0000x reference)
#include <cuda_runtime.h>

// FrequencyDecomposition: blocked 8x8 DCT -> zigzag band masks -> D*Y*D^T per band.
// out[3][B][C][H][W]: band0=low, band1=mid, band2=high.
// Lane-pair formulation: 2 threads per 8x8 block, each owns 4 columns (32 floats).
// R13: persistent CTAs (768 x 8 tiles) + one-tile register prefetch so the DRAM
// read stream stays continuous while compute/store phases run.

__device__ __forceinline__ void dct8(const float x[8], float y[8]) {
    const float A0 = 0.35355339059327373f;
    const float C1 = 0.4903926402016152f;
    const float C2 = 0.46193976625564337f;
    const float C3 = 0.4157348061512726f;
    const float C5 = 0.2777851165098011f;
    const float C6 = 0.19134171618254492f;
    const float C7 = 0.09754516100806417f;
    float s0 = x[0] + x[7], s1 = x[1] + x[6], s2 = x[2] + x[5], s3 = x[3] + x[4];
    float d0 = x[0] - x[7], d1 = x[1] - x[6], d2 = x[2] - x[5], d3 = x[3] - x[4];
    float t0 = s0 + s3, t1 = s1 + s2, t2 = s0 - s3, t3 = s1 - s2;
    y[0] = A0 * (t0 + t1);
    y[4] = A0 * (t0 - t1);
    y[2] = C2 * t2 + C6 * t3;
    y[6] = C6 * t2 - C2 * t3;
    y[1] = C1 * d0 + C3 * d1 + C5 * d2 + C7 * d3;
    y[3] = C3 * d0 - C7 * d1 - C1 * d2 - C5 * d3;
    y[5] = C5 * d0 - C1 * d1 + C7 * d2 + C3 * d3;
    y[7] = C7 * d0 - C5 * d1 + C3 * d2 - C1 * d3;
}

template<unsigned long long MASK>
__device__ __forceinline__ void band_rows(const float cf[32], float Z[32], int h) {
    #pragma unroll
    for (int i = 0; i < 8; ++i) {
        const unsigned rowm = (unsigned)((MASK >> (i * 8)) & 0xFF);
        if (rowm == 0u) {
            #pragma unroll
            for (int p = 0; p < 4; ++p) Z[i * 4 + p] = 0.0f;
        } else {
            float own[4], oth[4];
            #pragma unroll
            for (int p = 0; p < 4; ++p) {
                own[p] = cf[i * 4 + p];
                oth[p] = __shfl_xor_sync(0xFFFFFFFFu, own[p], 1);
            }
            float x[8];
            #pragma unroll
            for (int p = 0; p < 4; ++p) {
                float lo = h ? oth[p] : own[p];   // global cols 0..3
                float hi = h ? own[p] : oth[p];   // global cols 4..7
                x[p]     = ((rowm >> p) & 1u)       ? lo : 0.0f;
                x[4 + p] = ((rowm >> (4 + p)) & 1u) ? hi : 0.0f;
            }
            float y[8];
            dct8(x, y);
            #pragma unroll
            for (int p = 0; p < 4; ++p) Z[i * 4 + p] = h ? y[4 + p] : y[p];
        }
    }
}

__device__ __forceinline__ void band_cols_store(float Z[32], float* __restrict__ dst) {
    #pragma unroll
    for (int c = 0; c < 4; ++c) {
        float in[8], o[8];
        #pragma unroll
        for (int i = 0; i < 8; ++i) in[i] = Z[i * 4 + c];
        dct8(in, o);
        #pragma unroll
        for (int i = 0; i < 8; ++i) Z[i * 4 + c] = o[i];
    }
    #pragma unroll
    for (int r = 0; r < 8; ++r) {
        float4 v = make_float4(Z[r*4+0], Z[r*4+1], Z[r*4+2], Z[r*4+3]);
        *reinterpret_cast<float4*>(dst + (size_t)r * 512) = v;
    }
}

// tile t (0..6143): img = t>>6, block-row = t&63. Thread offset: b8 + h*4 cols.
__device__ __forceinline__ size_t tile_base(int t, int thrOff) {
    return (size_t)(t >> 6) * (512 * 512)
         + (size_t)(t & 63) * 8 * 512
         + (size_t)thrOff;
}

__device__ __forceinline__ void load_tile(const float* __restrict__ src, float P[32]) {
    #pragma unroll
    for (int r = 0; r < 8; ++r) {
        float4 v = *reinterpret_cast<const float4*>(src + (size_t)r * 512);
        P[r*4+0] = v.x; P[r*4+1] = v.y; P[r*4+2] = v.z; P[r*4+3] = v.w;
    }
}

#define GRID_CTAS 768
#define TILES     6144
#define TILES_PER_CTA (TILES / GRID_CTAS)   // 8

__global__ __launch_bounds__(128, 4)
void freqdec_kernel(const float* __restrict__ x, float* __restrict__ out)
{
    const int tid = threadIdx.x;
    const int h   = tid & 1;                    // half: 0 -> cols 0..3, 1 -> cols 4..7
    const int thrOff = (tid >> 1) * 8 + h * 4;  // column offset within tile row
    const size_t N = (size_t)32 * 3 * 512 * 512;

    int t = blockIdx.x;                         // this CTA's tile sequence: t, t+768, ...
    float X[32], P[32];
    load_tile(x + tile_base(t, thrOff), X);

    #pragma unroll 1
    for (int it = 0; it < TILES_PER_CTA; ++it) {
        const int tn = t + GRID_CTAS;
        // ---- prefetch next tile while this tile computes/stores ----
        if (it + 1 < TILES_PER_CTA)
            load_tile(x + tile_base(tn, thrOff), P);

        const size_t base = tile_base(t, thrOff);

        // ---- forward col DCT (local): X <- D * X ----
        #pragma unroll
        for (int c = 0; c < 4; ++c) {
            float in[8], o[8];
            #pragma unroll
            for (int i = 0; i < 8; ++i) in[i] = X[i * 4 + c];
            dct8(in, o);
            #pragma unroll
            for (int i = 0; i < 8; ++i) X[i * 4 + c] = o[i];
        }
        // ---- forward row DCT (shfl): X <- cf ----
        band_rows<0xFFFFFFFFFFFFFFFFULL>(X, X, h);

        // ---- three masked reconstructions ----
        float Z[32];
        band_rows<0x0000000103070F3FULL>(X, Z, h);      // low  (zigzag < 16)
        band_cols_store(Z, out + base);
        band_rows<0x030F1F3E7CF8F0C0ULL>(X, Z, h);      // mid
        band_cols_store(Z, out + N + base);
        band_rows<0xFCF0E0C080000000ULL>(X, Z, h);      // high (zigzag >= 48)
        band_cols_store(Z, out + 2 * N + base);

        // ---- rotate prefetch buffer in ----
        #pragma unroll
        for (int i = 0; i < 32; ++i) X[i] = P[i];
        t = tn;
    }
}

extern "C" void kernel_launch(void* const* d_in, const int* in_sizes, int n_in,
                              void* d_out, int out_size)
{
    const float* x = (const float*)d_in[0];
    float* out = (float*)d_out;
    (void)in_sizes; (void)n_in; (void)out_size;

    freqdec_kernel<<<GRID_CTAS, 128>>>(x, out);
}

// round 14
// speedup vs baseline: 1.1525x; 1.1525x over previous
#include <cuda_runtime.h>

// FrequencyDecomposition: blocked 8x8 DCT -> zigzag band masks -> D*Y*D^T per band.
// out[3][B][C][H][W]: band0=low, band1=mid, band2=high.
// Lane-pair formulation: 2 threads per 8x8 block, each owns 4 columns (32 floats).
// Column transforms are thread-local; row transforms exchange half-rows with
// shfl.xor(1). All global loads/stores fully coalesced (contiguous 16B/lane).
// FINAL (R9 config): measured HBM-roofline-bound at ~6.3 TB/s effective.
// Probed and rejected: streaming hints (R10), occ=6 (R11), persistent+prefetch (R13).

__device__ __forceinline__ void dct8(const float x[8], float y[8]) {
    const float A0 = 0.35355339059327373f;
    const float C1 = 0.4903926402016152f;
    const float C2 = 0.46193976625564337f;
    const float C3 = 0.4157348061512726f;
    const float C5 = 0.2777851165098011f;
    const float C6 = 0.19134171618254492f;
    const float C7 = 0.09754516100806417f;
    float s0 = x[0] + x[7], s1 = x[1] + x[6], s2 = x[2] + x[5], s3 = x[3] + x[4];
    float d0 = x[0] - x[7], d1 = x[1] - x[6], d2 = x[2] - x[5], d3 = x[3] - x[4];
    float t0 = s0 + s3, t1 = s1 + s2, t2 = s0 - s3, t3 = s1 - s2;
    y[0] = A0 * (t0 + t1);
    y[4] = A0 * (t0 - t1);
    y[2] = C2 * t2 + C6 * t3;
    y[6] = C6 * t2 - C2 * t3;
    y[1] = C1 * d0 + C3 * d1 + C5 * d2 + C7 * d3;
    y[3] = C3 * d0 - C7 * d1 - C1 * d2 - C5 * d3;
    y[5] = C5 * d0 - C1 * d1 + C7 * d2 + C3 * d3;
    y[7] = C7 * d0 - C5 * d1 + C3 * d2 - C1 * d3;
}

// Row-transform stage: Z = rowDCT(MASK o cf). cf/Z hold this thread's 4 columns
// (global cols h*4..h*4+3) of 8 rows. Half-rows exchanged with the pair lane.
// Rows whose full 8-bit mask is zero are skipped at compile time.
template<unsigned long long MASK>
__device__ __forceinline__ void band_rows(const float cf[32], float Z[32], int h) {
    #pragma unroll
    for (int i = 0; i < 8; ++i) {
        const unsigned rowm = (unsigned)((MASK >> (i * 8)) & 0xFF);
        if (rowm == 0u) {
            #pragma unroll
            for (int p = 0; p < 4; ++p) Z[i * 4 + p] = 0.0f;
        } else {
            float own[4], oth[4];
            #pragma unroll
            for (int p = 0; p < 4; ++p) {
                own[p] = cf[i * 4 + p];
                oth[p] = __shfl_xor_sync(0xFFFFFFFFu, own[p], 1);
            }
            float x[8];
            #pragma unroll
            for (int p = 0; p < 4; ++p) {
                float lo = h ? oth[p] : own[p];   // global cols 0..3
                float hi = h ? own[p] : oth[p];   // global cols 4..7
                x[p]     = ((rowm >> p) & 1u)       ? lo : 0.0f;  // compile-time mask
                x[4 + p] = ((rowm >> (4 + p)) & 1u) ? hi : 0.0f;
            }
            float y[8];
            dct8(x, y);
            #pragma unroll
            for (int p = 0; p < 4; ++p) Z[i * 4 + p] = h ? y[4 + p] : y[p];
        }
    }
}

// Column transform (thread-local) on Z in place, then 8 coalesced float4 stores.
__device__ __forceinline__ void band_cols_store(float Z[32], float* __restrict__ dst) {
    #pragma unroll
    for (int c = 0; c < 4; ++c) {
        float in[8], o[8];
        #pragma unroll
        for (int i = 0; i < 8; ++i) in[i] = Z[i * 4 + c];
        dct8(in, o);
        #pragma unroll
        for (int i = 0; i < 8; ++i) Z[i * 4 + c] = o[i];
    }
    #pragma unroll
    for (int r = 0; r < 8; ++r) {
        float4 v = make_float4(Z[r*4+0], Z[r*4+1], Z[r*4+2], Z[r*4+3]);
        *reinterpret_cast<float4*>(dst + (size_t)r * 512) = v;
    }
}

__global__ __launch_bounds__(128, 5)
void freqdec_kernel(const float* __restrict__ x, float* __restrict__ out)
{
    const int tid = threadIdx.x;
    const int h   = tid & 1;           // half: 0 -> cols 0..3, 1 -> cols 4..7
    const int b   = tid >> 1;          // block-col 0..63
    const int rb  = blockIdx.x;        // block-row 0..63
    const int img = blockIdx.y;        // 0..95 (B*C)

    const size_t base = (size_t)img * (512 * 512)
                      + (size_t)rb * 8 * 512
                      + (size_t)b * 8 + (size_t)h * 4;
    const float* src = x + base;

    // ---- load: 8 coalesced LDG.128 (lane l covers byte l*16 of a 512B span) ----
    float X[32];
    #pragma unroll
    for (int r = 0; r < 8; ++r) {
        float4 v = *reinterpret_cast<const float4*>(src + (size_t)r * 512);
        X[r*4+0] = v.x; X[r*4+1] = v.y; X[r*4+2] = v.z; X[r*4+3] = v.w;
    }

    // ---- forward col DCT (local): X <- D * X ----
    #pragma unroll
    for (int c = 0; c < 4; ++c) {
        float in[8], o[8];
        #pragma unroll
        for (int i = 0; i < 8; ++i) in[i] = X[i * 4 + c];
        dct8(in, o);
        #pragma unroll
        for (int i = 0; i < 8; ++i) X[i * 4 + c] = o[i];
    }
    // ---- forward row DCT (shfl): X <- cf = (D X) * D^T ----
    band_rows<0xFFFFFFFFFFFFFFFFULL>(X, X, h);

    // ---- three masked reconstructions ----
    const size_t N = (size_t)32 * 3 * 512 * 512;  // 25165824
    float Z[32];
    band_rows<0x0000000103070F3FULL>(X, Z, h);      // low  (zigzag < 16)
    band_cols_store(Z, out + base);
    band_rows<0x030F1F3E7CF8F0C0ULL>(X, Z, h);      // mid
    band_cols_store(Z, out + N + base);
    band_rows<0xFCF0E0C080000000ULL>(X, Z, h);      // high (zigzag >= 48)
    band_cols_store(Z, out + 2 * N + base);
}

extern "C" void kernel_launch(void* const* d_in, const int* in_sizes, int n_in,
                              void* d_out, int out_size)
{
    const float* x = (const float*)d_in[0];
    float* out = (float*)d_out;
    (void)in_sizes; (void)n_in; (void)out_size;

    dim3 grid(64, 96);   // (block-rows, B*C); 128 threads = 64 blocks * 2 lanes
    freqdec_kernel<<<grid, 128>>>(x, out);
}